// round 12
// baseline (speedup 1.0000x reference)
#include <cuda_runtime.h>
#include <cuda_fp16.h>
#include <math.h>
#include <cstdint>

#define NNODES 100000
#define NEDGES 1600000
#define D 128

// Scratch (allocation-free: __device__ globals)
__device__ __align__(16) __half g_h[NNODES * D];
__device__ __align__(16) __half g_y[NNODES * D];
__device__ __align__(16) __half g_whi[5 * 128 * 128];
__device__ int g_cnt[NNODES];
__device__ int g_off[NNODES + 1];
__device__ int g_bsum[128];
__device__ int g_srcs[NEDGES];

// ---------------------------------------------------------------------------
// helpers
// ---------------------------------------------------------------------------
__device__ __forceinline__ uint32_t smem_u32(const void* p) {
    uint32_t a;
    asm("{ .reg .u64 t; cvta.to.shared.u64 t, %1; cvt.u32.u64 %0, t; }"
        : "=r"(a) : "l"(p));
    return a;
}

#define LDSM4(r, addr) \
    asm volatile("ldmatrix.sync.aligned.m8n8.x4.shared.b16 {%0,%1,%2,%3}, [%4];" \
        : "=r"((r)[0]), "=r"((r)[1]), "=r"((r)[2]), "=r"((r)[3]) : "r"(addr))

#define MMA_F16(d, a, b) \
    asm volatile("mma.sync.aligned.m16n8k16.row.col.f32.f16.f16.f32 " \
        "{%0,%1,%2,%3}, {%4,%5,%6,%7}, {%8,%9}, {%0,%1,%2,%3};" \
        : "+f"((d)[0]), "+f"((d)[1]), "+f"((d)[2]), "+f"((d)[3]) \
        : "r"((a)[0]), "r"((a)[1]), "r"((a)[2]), "r"((a)[3]), \
          "r"((b)[0]), "r"((b)[1]))

__device__ __forceinline__ bool edges_is64(const int* E) {
    return (E[1] == 0) && (E[3] == 0) && (E[5] == 0) && (E[7] == 0);
}

__device__ __forceinline__ float4 h4_to_f4(uint2 u) {
    const float2 a = __half22float2(*(__half2*)&u.x);
    const float2 b = __half22float2(*(__half2*)&u.y);
    return make_float4(a.x, a.y, b.x, b.y);
}
__device__ __forceinline__ uint2 f4_to_h4(float4 v) {
    uint2 u;
    __half2 a = __floats2half2_rn(v.x, v.y);
    __half2 b = __floats2half2_rn(v.z, v.w);
    u.x = *(uint32_t*)&a; u.y = *(uint32_t*)&b;
    return u;
}
#define F4ADD(a, b) { (a).x += (b).x; (a).y += (b).y; (a).z += (b).z; (a).w += (b).w; }

// ---------------------------------------------------------------------------
// one-time converts, single launch:
//   x -> fp16, 5x W -> fp16 ([n][k]), zero g_cnt
// ---------------------------------------------------------------------------
struct WPtrs { const float* w[5]; };

__global__ void cvt_all_kernel(const float* __restrict__ X, __half* __restrict__ O,
                               WPtrs p, __half* __restrict__ HI) {
    const int i = blockIdx.x * blockDim.x + threadIdx.x;
    if (i < NNODES * 32)
        ((uint2*)O)[i] = f4_to_h4(((const float4*)X)[i]);
    if (i < NNODES) g_cnt[i] = 0;
    if (i < 5 * 16384) {
        const int s = i >> 14;
        const int idx = i & 16383;
        const int n = idx & 127, k = idx >> 7;
        HI[s * 16384 + n * 128 + k] = __float2half_rn(p.w[s][k * 128 + n]);
    }
}

// ---------------------------------------------------------------------------
// CSR build: histogram -> 2-kernel scan -> scatter
// ---------------------------------------------------------------------------
__global__ void hist_kernel(const int* __restrict__ E) {
    int e = blockIdx.x * blockDim.x + threadIdx.x;
    if (e >= NEDGES) return;
    const int dst = edges_is64(E) ? E[2 * (NEDGES + e)] : E[NEDGES + e];
    atomicAdd(&g_cnt[dst], 1);
}

__global__ void scan1_kernel() {
    __shared__ int wsum[32];
    const int tid = threadIdx.x;
    const int idx = blockIdx.x * 1024 + tid;
    int v = (idx < NNODES) ? g_cnt[idx] : 0;
    #pragma unroll
    for (int o = 16; o; o >>= 1) v += __shfl_down_sync(0xffffffffu, v, o);
    if ((tid & 31) == 0) wsum[tid >> 5] = v;
    __syncthreads();
    if (tid < 32) {
        int s = wsum[tid];
        #pragma unroll
        for (int o = 16; o; o >>= 1) s += __shfl_down_sync(0xffffffffu, s, o);
        if (tid == 0) g_bsum[blockIdx.x] = s;
    }
}

__global__ void scan2_kernel() {
    __shared__ int s[1024];
    __shared__ int sbase;
    const int tid = threadIdx.x;
    const int b = blockIdx.x;
    const int idx = b * 1024 + tid;
    const int c = (idx < NNODES) ? g_cnt[idx] : 0;
    s[tid] = c;
    if (tid < 32) {
        int acc = 0;
        for (int j = tid; j < b; j += 32) acc += g_bsum[j];
        #pragma unroll
        for (int o = 16; o; o >>= 1) acc += __shfl_down_sync(0xffffffffu, acc, o);
        if (tid == 0) sbase = acc;
    }
    __syncthreads();
    for (int o = 1; o < 1024; o <<= 1) {
        int t = (tid >= o) ? s[tid - o] : 0;
        __syncthreads();
        s[tid] += t;
        __syncthreads();
    }
    if (idx < NNODES) {
        const int excl = sbase + s[tid] - c;
        g_off[idx] = excl;
        g_cnt[idx] = excl;
    }
    if (b == 0 && tid == 0) g_off[NNODES] = NEDGES;
}

__global__ void scatter_kernel(const int* __restrict__ E) {
    int e = blockIdx.x * blockDim.x + threadIdx.x;
    if (e >= NEDGES) return;
    int src, dst;
    if (edges_is64(E)) { src = E[2 * e]; dst = E[2 * (NEDGES + e)]; }
    else               { src = E[e];     dst = E[NEDGES + e]; }
    const int pos = atomicAdd(&g_cnt[dst], 1);
    g_srcs[pos] = src;
}

// ---------------------------------------------------------------------------
// GEMM smem layout (single-fp16 weights)
// ---------------------------------------------------------------------------
#define STRIDE  272
#define SA      0
#define SB_HI   17408
#define SM_BIAS 52224
#define SM_TOT  52736

// ---- common GEMM body: B fill, mainloop (16x64 warp tiles), epilogue ----
__device__ __forceinline__ void gemm_body(
    char* smem, const __half* __restrict__ WH,
    const float* __restrict__ bias, __half* __restrict__ Y,
    int tid, int wid, int lane, int base)
{
    if (tid < 128) *(float*)(smem + SM_BIAS + tid * 4) = bias[tid];

    // B tile: pure fp16 copy (preconverted, [n][k] layout)
    {
        const uint4* WH4 = (const uint4*)WH;
        #pragma unroll
        for (int idx = tid; idx < 2048; idx += 256) {
            const int n = idx >> 4, g = idx & 15;
            *(uint4*)(smem + SB_HI + n * STRIDE + g * 16) = WH4[idx];
        }
    }
    __syncthreads();

    const uint32_t sb = smem_u32(smem);
    const int wr = wid & 3;       // 16-row group
    const int wc = wid >> 2;      // 64-col half

    const uint32_t a_base = sb + (uint32_t)((wr * 16 + (lane & 15)) * STRIDE
                                            + ((lane >> 4) << 4));
    const uint32_t b_base = sb + SB_HI +
        (uint32_t)((wc * 64 + (lane & 7) + ((lane & 16) ? 8 : 0)) * STRIDE
                   + ((lane & 8) ? 16 : 0));

    float acc[8][4];
    #pragma unroll
    for (int n = 0; n < 8; n++)
        #pragma unroll
        for (int j = 0; j < 4; j++) acc[n][j] = 0.f;

    #pragma unroll
    for (int ks = 0; ks < 8; ks++) {
        const uint32_t kb = ks * 32;
        uint32_t ah[4], bh[8][2];
        LDSM4(ah, a_base + SA + kb);
        #pragma unroll
        for (int u = 0; u < 4; u++) {
            uint32_t r[4];
            LDSM4(r, b_base + u * 16 * STRIDE + kb);
            bh[2 * u][0] = r[0]; bh[2 * u][1] = r[1];
            bh[2 * u + 1][0] = r[2]; bh[2 * u + 1][1] = r[3];
        }
        #pragma unroll
        for (int n = 0; n < 8; n++)
            MMA_F16(acc[n], ah, bh[n]);
    }

    // epilogue: bias + relu, store fp16
    const float* sBias = (const float*)(smem + SM_BIAS);
    const int r0 = base + wr * 16 + (lane >> 2);
    #pragma unroll
    for (int n = 0; n < 8; n++) {
        const int col = wc * 64 + n * 8 + 2 * (lane & 3);
        const float b0 = sBias[col], b1 = sBias[col + 1];
        const float v0 = fmaxf(acc[n][0] + b0, 0.f);
        const float v1 = fmaxf(acc[n][1] + b1, 0.f);
        const float v2 = fmaxf(acc[n][2] + b0, 0.f);
        const float v3 = fmaxf(acc[n][3] + b1, 0.f);
        if (r0 < NNODES) {
            const __half2 h = __floats2half2_rn(v0, v1);
            *(uint32_t*)(Y + (size_t)r0 * 128 + col) = *(const uint32_t*)&h;
        }
        if (r0 + 8 < NNODES) {
            const __half2 h = __floats2half2_rn(v2, v3);
            *(uint32_t*)(Y + (size_t)(r0 + 8) * 128 + col) = *(const uint32_t*)&h;
        }
    }
}

// ---------------------------------------------------------------------------
// Fused: A = (1+eps)*X[node] + sum_neighbors X[j]  (CSR gather, MLP=2), then GEMM.
// ---------------------------------------------------------------------------
__global__ void __launch_bounds__(256, 3)
agg_gemm_kernel(const __half* __restrict__ X,
                const float* __restrict__ eps,
                const __half* __restrict__ WH,
                const float* __restrict__ bias, __half* __restrict__ Y) {
    extern __shared__ char smem[];
    const int tid = threadIdx.x;
    const int wid = tid >> 5;
    const int lane = tid & 31;
    const int base = blockIdx.x * 64;

    // A tile = aggregation (warp per node; 8 nodes per warp)
    {
        const float s = 1.0f + *eps;
        const uint2* X2 = (const uint2*)X;
        #pragma unroll
        for (int i = 0; i < 8; i++) {
            const int rl = (wid << 3) + i;
            const int node = base + rl;
            float4 acc0 = make_float4(0.f, 0.f, 0.f, 0.f);
            if (node < NNODES) {
                const float4 a = h4_to_f4(X2[(size_t)node * 32 + lane]);
                acc0 = make_float4(a.x * s, a.y * s, a.z * s, a.w * s);
                float4 acc1 = make_float4(0.f, 0.f, 0.f, 0.f);
                const int end = g_off[node + 1];
                int j = g_off[node];
                for (; j + 1 < end; j += 2) {
                    const float4 v0 = h4_to_f4(X2[(size_t)g_srcs[j] * 32 + lane]);
                    const float4 v1 = h4_to_f4(X2[(size_t)g_srcs[j + 1] * 32 + lane]);
                    F4ADD(acc0, v0);
                    F4ADD(acc1, v1);
                }
                if (j < end) {
                    const float4 v0 = h4_to_f4(X2[(size_t)g_srcs[j] * 32 + lane]);
                    F4ADD(acc0, v0);
                }
                F4ADD(acc0, acc1);
            }
            *(uint2*)(smem + SA + rl * STRIDE + lane * 8) = f4_to_h4(acc0);
        }
    }
    gemm_body(smem, WH, bias, Y, tid, wid, lane, base);
}

// ---------------------------------------------------------------------------
// Plain GEMM: A tile = straight fp16 row copy
// ---------------------------------------------------------------------------
__global__ void __launch_bounds__(256, 3)
mma_gemm_kernel(const __half* __restrict__ X,
                const __half* __restrict__ WH,
                const float* __restrict__ bias, __half* __restrict__ Y) {
    extern __shared__ char smem[];
    const int tid = threadIdx.x;
    const int wid = tid >> 5;
    const int lane = tid & 31;
    const int base = blockIdx.x * 64;

    {
        const uint4* X16 = (const uint4*)X;
        #pragma unroll
        for (int idx = tid; idx < 1024; idx += 256) {
            const int rl = idx >> 4, g = idx & 15;
            const int row = base + rl;
            uint4 v = make_uint4(0u, 0u, 0u, 0u);
            if (row < NNODES) v = X16[(size_t)row * 16 + g];
            *(uint4*)(smem + SA + rl * STRIDE + g * 16) = v;
        }
    }
    gemm_body(smem, WH, bias, Y, tid, wid, lane, base);
}

// ---------------------------------------------------------------------------
// Final layer: out = log_softmax(X(fp16) @ W[128,40] + b)
// ---------------------------------------------------------------------------
#define G40_SMEM ((128 * 40 + 64 * 128 + 64 * 40 + 64) * 4)   // 63744

__global__ void gemm40_softmax_kernel(const __half* __restrict__ X,
                                      const float* __restrict__ W,
                                      const float* __restrict__ bias,
                                      float* __restrict__ out) {
    extern __shared__ float fsm[];
    float* sW = fsm;                       // 128*40
    float* sX = fsm + 128 * 40;            // 64*128
    float* sOut = sX + 64 * 128;           // 64*40
    float* sLs = sOut + 64 * 40;           // 64

    const int tid = threadIdx.x;
    const int base = blockIdx.x * 64;

    float4* sW4 = (float4*)sW;
    const float4* W4 = (const float4*)W;
    #pragma unroll 4
    for (int i = tid; i < 128 * 10; i += 80) sW4[i] = W4[i];

    float4* sX4 = (float4*)sX;
    const uint2* X2 = (const uint2*)X;
    #pragma unroll 4
    for (int i = tid; i < 64 * 32; i += 80) {
        const int rl = i >> 5;
        const int row = base + rl;
        sX4[i] = (row < NNODES) ? h4_to_f4(X2[(size_t)row * 32 + (i & 31)])
                                : make_float4(0.f, 0.f, 0.f, 0.f);
    }
    __syncthreads();

    const int cg = tid % 5;
    const int rg = tid / 5;

    float acc[4][8];
    #pragma unroll
    for (int r = 0; r < 4; r++)
        #pragma unroll
        for (int j = 0; j < 8; j++) acc[r][j] = 0.f;

    #pragma unroll 2
    for (int k0 = 0; k0 < 128; k0 += 4) {
        float4 xv[4];
        #pragma unroll
        for (int r = 0; r < 4; r++)
            xv[r] = sX4[(rg * 4 + r) * 32 + (k0 >> 2)];
        #pragma unroll
        for (int j = 0; j < 4; j++) {
            const float4 wa = sW4[(k0 + j) * 10 + cg * 2];
            const float4 wb = sW4[(k0 + j) * 10 + cg * 2 + 1];
            #pragma unroll
            for (int r = 0; r < 4; r++) {
                const float xs = (j == 0) ? xv[r].x :
                                 (j == 1) ? xv[r].y :
                                 (j == 2) ? xv[r].z : xv[r].w;
                acc[r][0] = fmaf(xs, wa.x, acc[r][0]);
                acc[r][1] = fmaf(xs, wa.y, acc[r][1]);
                acc[r][2] = fmaf(xs, wa.z, acc[r][2]);
                acc[r][3] = fmaf(xs, wa.w, acc[r][3]);
                acc[r][4] = fmaf(xs, wb.x, acc[r][4]);
                acc[r][5] = fmaf(xs, wb.y, acc[r][5]);
                acc[r][6] = fmaf(xs, wb.z, acc[r][6]);
                acc[r][7] = fmaf(xs, wb.w, acc[r][7]);
            }
        }
    }

    float bb[8];
    #pragma unroll
    for (int j = 0; j < 8; j++) bb[j] = bias[cg * 8 + j];

    #pragma unroll
    for (int r = 0; r < 4; r++) {
        const int rl = rg * 4 + r;
        float4 v0 = make_float4(acc[r][0] + bb[0], acc[r][1] + bb[1],
                                acc[r][2] + bb[2], acc[r][3] + bb[3]);
        float4 v1 = make_float4(acc[r][4] + bb[4], acc[r][5] + bb[5],
                                acc[r][6] + bb[6], acc[r][7] + bb[7]);
        *(float4*)(sOut + rl * 40 + cg * 8) = v0;
        *(float4*)(sOut + rl * 40 + cg * 8 + 4) = v1;
    }
    __syncthreads();

    if (tid < 64 && base + tid < NNODES) {
        const float* p = sOut + tid * 40;
        float m = p[0];
        #pragma unroll 8
        for (int c = 1; c < 40; c++) m = fmaxf(m, p[c]);
        float s = 0.f;
        #pragma unroll 8
        for (int c = 0; c < 40; c++) s += expf(p[c] - m);
        sLs[tid] = m + logf(s);
    }
    __syncthreads();

    #pragma unroll
    for (int r = 0; r < 4; r++) {
        const int rl = rg * 4 + r;
        const int row = base + rl;
        if (row < NNODES) {
            const float ls = sLs[rl];
            float4 v0 = make_float4(acc[r][0] + bb[0] - ls, acc[r][1] + bb[1] - ls,
                                    acc[r][2] + bb[2] - ls, acc[r][3] + bb[3] - ls);
            float4 v1 = make_float4(acc[r][4] + bb[4] - ls, acc[r][5] + bb[5] - ls,
                                    acc[r][6] + bb[6] - ls, acc[r][7] + bb[7] - ls);
            float4* o = (float4*)(out + (size_t)row * 40 + cg * 8);
            o[0] = v0;
            o[1] = v1;
        }
    }
}

// ---------------------------------------------------------------------------
extern "C" void kernel_launch(void* const* d_in, const int* in_sizes, int n_in,
                              void* d_out, int out_size) {
    const float* x     = (const float*)d_in[0];
    const int*   edges = (const int*)d_in[1];
    const float* W1[3] = {(const float*)d_in[2], (const float*)d_in[7],  (const float*)d_in[12]};
    const float* b1[3] = {(const float*)d_in[3], (const float*)d_in[8],  (const float*)d_in[13]};
    const float* W2[3] = {(const float*)d_in[4], (const float*)d_in[9],  (const float*)d_in[14]};
    const float* b2[3] = {(const float*)d_in[5], (const float*)d_in[10], (const float*)d_in[15]};
    const float* ep[3] = {(const float*)d_in[6], (const float*)d_in[11], (const float*)d_in[16]};
    float* out = (float*)d_out;

    void *ph, *py, *phi;
    cudaGetSymbolAddress(&ph, g_h);
    cudaGetSymbolAddress(&py, g_y);
    cudaGetSymbolAddress(&phi, g_whi);
    __half* h   = (__half*)ph;
    __half* y   = (__half*)py;    // also holds x16 until layer-0 GEMM2
    __half* whi = (__half*)phi;

    cudaFuncSetAttribute(agg_gemm_kernel,
                         cudaFuncAttributeMaxDynamicSharedMemorySize, SM_TOT);
    cudaFuncSetAttribute(mma_gemm_kernel,
                         cudaFuncAttributeMaxDynamicSharedMemorySize, SM_TOT);
    cudaFuncSetAttribute(gemm40_softmax_kernel,
                         cudaFuncAttributeMaxDynamicSharedMemorySize, G40_SMEM);

    const int edge_blocks = (NEDGES + 255) / 256;           // 6250
    const int scan_blocks = (NNODES + 1023) / 1024;         // 98
    const int mm_blocks   = (NNODES + 63) / 64;             // 1563

    // ---- one-time converts (single launch) + CSR build ----
    WPtrs wp; wp.w[0] = W1[0]; wp.w[1] = W2[0]; wp.w[2] = W1[1];
    wp.w[3] = W2[1]; wp.w[4] = W1[2];
    cvt_all_kernel<<<(NNODES * 32 + 255) / 256, 256>>>(x, y, wp, whi);
    hist_kernel<<<edge_blocks, 256>>>(edges);
    scan1_kernel<<<scan_blocks, 1024>>>();
    scan2_kernel<<<scan_blocks, 1024>>>();
    scatter_kernel<<<edge_blocks, 256>>>(edges);

    // ---- layer 0 ----  (y currently holds x16)
    agg_gemm_kernel<<<mm_blocks, 256, SM_TOT>>>(y, ep[0], whi + 0 * 16384, b1[0], h);
    mma_gemm_kernel<<<mm_blocks, 256, SM_TOT>>>(h, whi + 1 * 16384, b2[0], y);
    // ---- layer 1 ----
    agg_gemm_kernel<<<mm_blocks, 256, SM_TOT>>>(y, ep[1], whi + 2 * 16384, b1[1], h);
    mma_gemm_kernel<<<mm_blocks, 256, SM_TOT>>>(h, whi + 3 * 16384, b2[1], y);
    // ---- layer 2 ----
    agg_gemm_kernel<<<mm_blocks, 256, SM_TOT>>>(y, ep[2], whi + 4 * 16384, b1[2], h);
    gemm40_softmax_kernel<<<mm_blocks, 80, G40_SMEM>>>(h, W2[2], b2[2], out);

    (void)in_sizes; (void)n_in; (void)out_size;
}

// round 13
// speedup vs baseline: 1.2528x; 1.2528x over previous
#include <cuda_runtime.h>
#include <cuda_fp16.h>
#include <math.h>
#include <cstdint>

#define NNODES 100000
#define NEDGES 1600000
#define D 128

// Scratch (allocation-free: __device__ globals)
__device__ __align__(16) __half g_h[NNODES * D];
__device__ __align__(16) __half g_y[NNODES * D];
__device__ __align__(16) __half g_whi[5 * 128 * 128];
__device__ int g_cnt[NNODES];
__device__ int g_off[NNODES + 1];
__device__ int g_bsum[128];
__device__ int g_srcs[NEDGES];

// ---------------------------------------------------------------------------
// helpers
// ---------------------------------------------------------------------------
__device__ __forceinline__ uint32_t smem_u32(const void* p) {
    uint32_t a;
    asm("{ .reg .u64 t; cvta.to.shared.u64 t, %1; cvt.u32.u64 %0, t; }"
        : "=r"(a) : "l"(p));
    return a;
}

#define LDSM4(r, addr) \
    asm volatile("ldmatrix.sync.aligned.m8n8.x4.shared.b16 {%0,%1,%2,%3}, [%4];" \
        : "=r"((r)[0]), "=r"((r)[1]), "=r"((r)[2]), "=r"((r)[3]) : "r"(addr))

#define MMA_F16(d, a, b) \
    asm volatile("mma.sync.aligned.m16n8k16.row.col.f32.f16.f16.f32 " \
        "{%0,%1,%2,%3}, {%4,%5,%6,%7}, {%8,%9}, {%0,%1,%2,%3};" \
        : "+f"((d)[0]), "+f"((d)[1]), "+f"((d)[2]), "+f"((d)[3]) \
        : "r"((a)[0]), "r"((a)[1]), "r"((a)[2]), "r"((a)[3]), \
          "r"((b)[0]), "r"((b)[1]))

__device__ __forceinline__ bool edges_is64(const int* E) {
    return (E[1] == 0) && (E[3] == 0) && (E[5] == 0) && (E[7] == 0);
}

__device__ __forceinline__ float4 h4_to_f4(uint2 u) {
    const float2 a = __half22float2(*(__half2*)&u.x);
    const float2 b = __half22float2(*(__half2*)&u.y);
    return make_float4(a.x, a.y, b.x, b.y);
}
__device__ __forceinline__ uint2 f4_to_h4(float4 v) {
    uint2 u;
    __half2 a = __floats2half2_rn(v.x, v.y);
    __half2 b = __floats2half2_rn(v.z, v.w);
    u.x = *(uint32_t*)&a; u.y = *(uint32_t*)&b;
    return u;
}
#define F4ADD(a, b) { (a).x += (b).x; (a).y += (b).y; (a).z += (b).z; (a).w += (b).w; }

// ---------------------------------------------------------------------------
// one-time converts, single launch:
//   x -> fp16, 5x W -> fp16 ([n][k]), zero g_cnt
// ---------------------------------------------------------------------------
struct WPtrs { const float* w[5]; };

__global__ void cvt_all_kernel(const float* __restrict__ X, __half* __restrict__ O,
                               WPtrs p, __half* __restrict__ HI) {
    const int i = blockIdx.x * blockDim.x + threadIdx.x;
    if (i < NNODES * 32)
        ((uint2*)O)[i] = f4_to_h4(((const float4*)X)[i]);
    if (i < NNODES) g_cnt[i] = 0;
    if (i < 5 * 16384) {
        const int s = i >> 14;
        const int idx = i & 16383;
        const int n = idx & 127, k = idx >> 7;
        HI[s * 16384 + n * 128 + k] = __float2half_rn(p.w[s][k * 128 + n]);
    }
}

// ---------------------------------------------------------------------------
// CSR build: histogram -> 2-kernel scan -> scatter
// ---------------------------------------------------------------------------
__global__ void hist_kernel(const int* __restrict__ E) {
    int e = blockIdx.x * blockDim.x + threadIdx.x;
    if (e >= NEDGES) return;
    const int dst = edges_is64(E) ? E[2 * (NEDGES + e)] : E[NEDGES + e];
    atomicAdd(&g_cnt[dst], 1);
}

__global__ void scan1_kernel() {
    __shared__ int wsum[32];
    const int tid = threadIdx.x;
    const int idx = blockIdx.x * 1024 + tid;
    int v = (idx < NNODES) ? g_cnt[idx] : 0;
    #pragma unroll
    for (int o = 16; o; o >>= 1) v += __shfl_down_sync(0xffffffffu, v, o);
    if ((tid & 31) == 0) wsum[tid >> 5] = v;
    __syncthreads();
    if (tid < 32) {
        int s = wsum[tid];
        #pragma unroll
        for (int o = 16; o; o >>= 1) s += __shfl_down_sync(0xffffffffu, s, o);
        if (tid == 0) g_bsum[blockIdx.x] = s;
    }
}

__global__ void scan2_kernel() {
    __shared__ int s[1024];
    __shared__ int sbase;
    const int tid = threadIdx.x;
    const int b = blockIdx.x;
    const int idx = b * 1024 + tid;
    const int c = (idx < NNODES) ? g_cnt[idx] : 0;
    s[tid] = c;
    if (tid < 32) {
        int acc = 0;
        for (int j = tid; j < b; j += 32) acc += g_bsum[j];
        #pragma unroll
        for (int o = 16; o; o >>= 1) acc += __shfl_down_sync(0xffffffffu, acc, o);
        if (tid == 0) sbase = acc;
    }
    __syncthreads();
    for (int o = 1; o < 1024; o <<= 1) {
        int t = (tid >= o) ? s[tid - o] : 0;
        __syncthreads();
        s[tid] += t;
        __syncthreads();
    }
    if (idx < NNODES) {
        const int excl = sbase + s[tid] - c;
        g_off[idx] = excl;
        g_cnt[idx] = excl;
    }
    if (b == 0 && tid == 0) g_off[NNODES] = NEDGES;
}

__global__ void scatter_kernel(const int* __restrict__ E) {
    int e = blockIdx.x * blockDim.x + threadIdx.x;
    if (e >= NEDGES) return;
    int src, dst;
    if (edges_is64(E)) { src = E[2 * e]; dst = E[2 * (NEDGES + e)]; }
    else               { src = E[e];     dst = E[NEDGES + e]; }
    const int pos = atomicAdd(&g_cnt[dst], 1);
    g_srcs[pos] = src;
}

// ---------------------------------------------------------------------------
// GEMM smem layout (single-fp16 weights)
// ---------------------------------------------------------------------------
#define STRIDE  272
#define SA      0
#define SB_HI   17408
#define SM_BIAS 52224
#define SM_TOT  52736

// ---- common GEMM body: B fill, software-pipelined mainloop, epilogue ----
__device__ __forceinline__ void gemm_body(
    char* smem, const __half* __restrict__ WH,
    const float* __restrict__ bias, __half* __restrict__ Y,
    int tid, int wid, int lane, int base)
{
    if (tid < 128) *(float*)(smem + SM_BIAS + tid * 4) = bias[tid];

    // B tile: pure fp16 copy (preconverted, [n][k] layout)
    {
        const uint4* WH4 = (const uint4*)WH;
        #pragma unroll
        for (int idx = tid; idx < 2048; idx += 256) {
            const int n = idx >> 4, g = idx & 15;
            *(uint4*)(smem + SB_HI + n * STRIDE + g * 16) = WH4[idx];
        }
    }
    __syncthreads();

    const uint32_t sb = smem_u32(smem);
    const int wr = wid & 3;       // 16-row group
    const int wc = wid >> 2;      // 64-col half

    const uint32_t a_base = sb + (uint32_t)((wr * 16 + (lane & 15)) * STRIDE
                                            + ((lane >> 4) << 4));
    const uint32_t b_base = sb + SB_HI +
        (uint32_t)((wc * 64 + (lane & 7) + ((lane & 16) ? 8 : 0)) * STRIDE
                   + ((lane & 8) ? 16 : 0));

    float acc[8][4];
    #pragma unroll
    for (int n = 0; n < 8; n++)
        #pragma unroll
        for (int j = 0; j < 4; j++) acc[n][j] = 0.f;

    // double-buffered fragment registers
    uint32_t ah[2][4], bh[2][8][2];

    // prologue: load k-step 0 into buffer 0
    LDSM4(ah[0], a_base);
    #pragma unroll
    for (int u = 0; u < 4; u++) {
        uint32_t r[4];
        LDSM4(r, b_base + u * 16 * STRIDE);
        bh[0][2 * u][0] = r[0]; bh[0][2 * u][1] = r[1];
        bh[0][2 * u + 1][0] = r[2]; bh[0][2 * u + 1][1] = r[3];
    }

    #pragma unroll
    for (int ks = 0; ks < 8; ks++) {
        const int cur = ks & 1, nxt = cur ^ 1;
        if (ks < 7) {
            const uint32_t kb = (ks + 1) * 32;
            LDSM4(ah[nxt], a_base + kb);
            #pragma unroll
            for (int u = 0; u < 4; u++) {
                uint32_t r[4];
                LDSM4(r, b_base + u * 16 * STRIDE + kb);
                bh[nxt][2 * u][0] = r[0]; bh[nxt][2 * u][1] = r[1];
                bh[nxt][2 * u + 1][0] = r[2]; bh[nxt][2 * u + 1][1] = r[3];
            }
        }
        #pragma unroll
        for (int n = 0; n < 8; n++)
            MMA_F16(acc[n], ah[cur], bh[cur][n]);
    }

    // epilogue: bias + relu, store fp16
    const float* sBias = (const float*)(smem + SM_BIAS);
    const int r0 = base + wr * 16 + (lane >> 2);
    #pragma unroll
    for (int n = 0; n < 8; n++) {
        const int col = wc * 64 + n * 8 + 2 * (lane & 3);
        const float b0 = sBias[col], b1 = sBias[col + 1];
        const float v0 = fmaxf(acc[n][0] + b0, 0.f);
        const float v1 = fmaxf(acc[n][1] + b1, 0.f);
        const float v2 = fmaxf(acc[n][2] + b0, 0.f);
        const float v3 = fmaxf(acc[n][3] + b1, 0.f);
        if (r0 < NNODES) {
            const __half2 h = __floats2half2_rn(v0, v1);
            *(uint32_t*)(Y + (size_t)r0 * 128 + col) = *(const uint32_t*)&h;
        }
        if (r0 + 8 < NNODES) {
            const __half2 h = __floats2half2_rn(v2, v3);
            *(uint32_t*)(Y + (size_t)(r0 + 8) * 128 + col) = *(const uint32_t*)&h;
        }
    }
}

// ---------------------------------------------------------------------------
// Fused: A = (1+eps)*X[node] + sum_neighbors X[j]  (CSR gather, MLP=2), then GEMM.
// ---------------------------------------------------------------------------
__global__ void __launch_bounds__(256, 2)
agg_gemm_kernel(const __half* __restrict__ X,
                const float* __restrict__ eps,
                const __half* __restrict__ WH,
                const float* __restrict__ bias, __half* __restrict__ Y) {
    extern __shared__ char smem[];
    const int tid = threadIdx.x;
    const int wid = tid >> 5;
    const int lane = tid & 31;
    const int base = blockIdx.x * 64;

    // A tile = aggregation (warp per node; 8 nodes per warp)
    {
        const float s = 1.0f + *eps;
        const uint2* X2 = (const uint2*)X;
        #pragma unroll
        for (int i = 0; i < 8; i++) {
            const int rl = (wid << 3) + i;
            const int node = base + rl;
            float4 acc0 = make_float4(0.f, 0.f, 0.f, 0.f);
            if (node < NNODES) {
                const float4 a = h4_to_f4(X2[(size_t)node * 32 + lane]);
                acc0 = make_float4(a.x * s, a.y * s, a.z * s, a.w * s);
                float4 acc1 = make_float4(0.f, 0.f, 0.f, 0.f);
                const int end = g_off[node + 1];
                int j = g_off[node];
                for (; j + 1 < end; j += 2) {
                    const float4 v0 = h4_to_f4(X2[(size_t)g_srcs[j] * 32 + lane]);
                    const float4 v1 = h4_to_f4(X2[(size_t)g_srcs[j + 1] * 32 + lane]);
                    F4ADD(acc0, v0);
                    F4ADD(acc1, v1);
                }
                if (j < end) {
                    const float4 v0 = h4_to_f4(X2[(size_t)g_srcs[j] * 32 + lane]);
                    F4ADD(acc0, v0);
                }
                F4ADD(acc0, acc1);
            }
            *(uint2*)(smem + SA + rl * STRIDE + lane * 8) = f4_to_h4(acc0);
        }
    }
    gemm_body(smem, WH, bias, Y, tid, wid, lane, base);
}

// ---------------------------------------------------------------------------
// Plain GEMM: A tile = straight fp16 row copy
// ---------------------------------------------------------------------------
__global__ void __launch_bounds__(256, 2)
mma_gemm_kernel(const __half* __restrict__ X,
                const __half* __restrict__ WH,
                const float* __restrict__ bias, __half* __restrict__ Y) {
    extern __shared__ char smem[];
    const int tid = threadIdx.x;
    const int wid = tid >> 5;
    const int lane = tid & 31;
    const int base = blockIdx.x * 64;

    {
        const uint4* X16 = (const uint4*)X;
        #pragma unroll
        for (int idx = tid; idx < 1024; idx += 256) {
            const int rl = idx >> 4, g = idx & 15;
            const int row = base + rl;
            uint4 v = make_uint4(0u, 0u, 0u, 0u);
            if (row < NNODES) v = X16[(size_t)row * 16 + g];
            *(uint4*)(smem + SA + rl * STRIDE + g * 16) = v;
        }
    }
    gemm_body(smem, WH, bias, Y, tid, wid, lane, base);
}

// ---------------------------------------------------------------------------
// Final layer: out = log_softmax(X(fp16) @ W[128,40] + b)
// ---------------------------------------------------------------------------
#define G40_SMEM ((128 * 40 + 64 * 128 + 64 * 40 + 64) * 4)   // 63744

__global__ void gemm40_softmax_kernel(const __half* __restrict__ X,
                                      const float* __restrict__ W,
                                      const float* __restrict__ bias,
                                      float* __restrict__ out) {
    extern __shared__ float fsm[];
    float* sW = fsm;                       // 128*40
    float* sX = fsm + 128 * 40;            // 64*128
    float* sOut = sX + 64 * 128;           // 64*40
    float* sLs = sOut + 64 * 40;           // 64

    const int tid = threadIdx.x;
    const int base = blockIdx.x * 64;

    float4* sW4 = (float4*)sW;
    const float4* W4 = (const float4*)W;
    #pragma unroll 4
    for (int i = tid; i < 128 * 10; i += 80) sW4[i] = W4[i];

    float4* sX4 = (float4*)sX;
    const uint2* X2 = (const uint2*)X;
    #pragma unroll 4
    for (int i = tid; i < 64 * 32; i += 80) {
        const int rl = i >> 5;
        const int row = base + rl;
        sX4[i] = (row < NNODES) ? h4_to_f4(X2[(size_t)row * 32 + (i & 31)])
                                : make_float4(0.f, 0.f, 0.f, 0.f);
    }
    __syncthreads();

    const int cg = tid % 5;
    const int rg = tid / 5;

    float acc[4][8];
    #pragma unroll
    for (int r = 0; r < 4; r++)
        #pragma unroll
        for (int j = 0; j < 8; j++) acc[r][j] = 0.f;

    #pragma unroll 2
    for (int k0 = 0; k0 < 128; k0 += 4) {
        float4 xv[4];
        #pragma unroll
        for (int r = 0; r < 4; r++)
            xv[r] = sX4[(rg * 4 + r) * 32 + (k0 >> 2)];
        #pragma unroll
        for (int j = 0; j < 4; j++) {
            const float4 wa = sW4[(k0 + j) * 10 + cg * 2];
            const float4 wb = sW4[(k0 + j) * 10 + cg * 2 + 1];
            #pragma unroll
            for (int r = 0; r < 4; r++) {
                const float xs = (j == 0) ? xv[r].x :
                                 (j == 1) ? xv[r].y :
                                 (j == 2) ? xv[r].z : xv[r].w;
                acc[r][0] = fmaf(xs, wa.x, acc[r][0]);
                acc[r][1] = fmaf(xs, wa.y, acc[r][1]);
                acc[r][2] = fmaf(xs, wa.z, acc[r][2]);
                acc[r][3] = fmaf(xs, wa.w, acc[r][3]);
                acc[r][4] = fmaf(xs, wb.x, acc[r][4]);
                acc[r][5] = fmaf(xs, wb.y, acc[r][5]);
                acc[r][6] = fmaf(xs, wb.z, acc[r][6]);
                acc[r][7] = fmaf(xs, wb.w, acc[r][7]);
            }
        }
    }

    float bb[8];
    #pragma unroll
    for (int j = 0; j < 8; j++) bb[j] = bias[cg * 8 + j];

    #pragma unroll
    for (int r = 0; r < 4; r++) {
        const int rl = rg * 4 + r;
        float4 v0 = make_float4(acc[r][0] + bb[0], acc[r][1] + bb[1],
                                acc[r][2] + bb[2], acc[r][3] + bb[3]);
        float4 v1 = make_float4(acc[r][4] + bb[4], acc[r][5] + bb[5],
                                acc[r][6] + bb[6], acc[r][7] + bb[7]);
        *(float4*)(sOut + rl * 40 + cg * 8) = v0;
        *(float4*)(sOut + rl * 40 + cg * 8 + 4) = v1;
    }
    __syncthreads();

    if (tid < 64 && base + tid < NNODES) {
        const float* p = sOut + tid * 40;
        float m = p[0];
        #pragma unroll 8
        for (int c = 1; c < 40; c++) m = fmaxf(m, p[c]);
        float s = 0.f;
        #pragma unroll 8
        for (int c = 0; c < 40; c++) s += expf(p[c] - m);
        sLs[tid] = m + logf(s);
    }
    __syncthreads();

    #pragma unroll
    for (int r = 0; r < 4; r++) {
        const int rl = rg * 4 + r;
        const int row = base + rl;
        if (row < NNODES) {
            const float ls = sLs[rl];
            float4 v0 = make_float4(acc[r][0] + bb[0] - ls, acc[r][1] + bb[1] - ls,
                                    acc[r][2] + bb[2] - ls, acc[r][3] + bb[3] - ls);
            float4 v1 = make_float4(acc[r][4] + bb[4] - ls, acc[r][5] + bb[5] - ls,
                                    acc[r][6] + bb[6] - ls, acc[r][7] + bb[7] - ls);
            float4* o = (float4*)(out + (size_t)row * 40 + cg * 8);
            o[0] = v0;
            o[1] = v1;
        }
    }
}

// ---------------------------------------------------------------------------
extern "C" void kernel_launch(void* const* d_in, const int* in_sizes, int n_in,
                              void* d_out, int out_size) {
    const float* x     = (const float*)d_in[0];
    const int*   edges = (const int*)d_in[1];
    const float* W1[3] = {(const float*)d_in[2], (const float*)d_in[7],  (const float*)d_in[12]};
    const float* b1[3] = {(const float*)d_in[3], (const float*)d_in[8],  (const float*)d_in[13]};
    const float* W2[3] = {(const float*)d_in[4], (const float*)d_in[9],  (const float*)d_in[14]};
    const float* b2[3] = {(const float*)d_in[5], (const float*)d_in[10], (const float*)d_in[15]};
    const float* ep[3] = {(const float*)d_in[6], (const float*)d_in[11], (const float*)d_in[16]};
    float* out = (float*)d_out;

    void *ph, *py, *phi;
    cudaGetSymbolAddress(&ph, g_h);
    cudaGetSymbolAddress(&py, g_y);
    cudaGetSymbolAddress(&phi, g_whi);
    __half* h   = (__half*)ph;
    __half* y   = (__half*)py;    // also holds x16 until layer-0 GEMM2
    __half* whi = (__half*)phi;

    cudaFuncSetAttribute(agg_gemm_kernel,
                         cudaFuncAttributeMaxDynamicSharedMemorySize, SM_TOT);
    cudaFuncSetAttribute(mma_gemm_kernel,
                         cudaFuncAttributeMaxDynamicSharedMemorySize, SM_TOT);
    cudaFuncSetAttribute(gemm40_softmax_kernel,
                         cudaFuncAttributeMaxDynamicSharedMemorySize, G40_SMEM);

    const int edge_blocks = (NEDGES + 255) / 256;           // 6250
    const int scan_blocks = (NNODES + 1023) / 1024;         // 98
    const int mm_blocks   = (NNODES + 63) / 64;             // 1563

    // ---- one-time converts (single launch) + CSR build ----
    WPtrs wp; wp.w[0] = W1[0]; wp.w[1] = W2[0]; wp.w[2] = W1[1];
    wp.w[3] = W2[1]; wp.w[4] = W1[2];
    cvt_all_kernel<<<(NNODES * 32 + 255) / 256, 256>>>(x, y, wp, whi);
    hist_kernel<<<edge_blocks, 256>>>(edges);
    scan1_kernel<<<scan_blocks, 1024>>>();
    scan2_kernel<<<scan_blocks, 1024>>>();
    scatter_kernel<<<edge_blocks, 256>>>(edges);

    // ---- layer 0 ----  (y currently holds x16)
    agg_gemm_kernel<<<mm_blocks, 256, SM_TOT>>>(y, ep[0], whi + 0 * 16384, b1[0], h);
    mma_gemm_kernel<<<mm_blocks, 256, SM_TOT>>>(h, whi + 1 * 16384, b2[0], y);
    // ---- layer 1 ----
    agg_gemm_kernel<<<mm_blocks, 256, SM_TOT>>>(y, ep[1], whi + 2 * 16384, b1[1], h);
    mma_gemm_kernel<<<mm_blocks, 256, SM_TOT>>>(h, whi + 3 * 16384, b2[1], y);
    // ---- layer 2 ----
    agg_gemm_kernel<<<mm_blocks, 256, SM_TOT>>>(y, ep[2], whi + 4 * 16384, b1[2], h);
    gemm40_softmax_kernel<<<mm_blocks, 80, G40_SMEM>>>(h, W2[2], b2[2], out);

    (void)in_sizes; (void)n_in; (void)out_size;
}

// round 14
// speedup vs baseline: 1.4729x; 1.1757x over previous
#include <cuda_runtime.h>
#include <cuda_fp16.h>
#include <math.h>
#include <cstdint>

#define NNODES 100000
#define NEDGES 1600000
#define D 128

// Scratch (allocation-free: __device__ globals)
__device__ __align__(16) __half g_h[NNODES * D];
__device__ __align__(16) __half g_y[NNODES * D];
__device__ __align__(16) __half g_aggr[NNODES * D];
__device__ __align__(16) __half g_whi[5 * 128 * 128];
__device__ int g_cnt[NNODES];
__device__ int g_off[NNODES + 1];
__device__ int g_bsum[128];
__device__ int g_srcs[NEDGES];

// ---------------------------------------------------------------------------
// helpers
// ---------------------------------------------------------------------------
__device__ __forceinline__ uint32_t smem_u32(const void* p) {
    uint32_t a;
    asm("{ .reg .u64 t; cvta.to.shared.u64 t, %1; cvt.u32.u64 %0, t; }"
        : "=r"(a) : "l"(p));
    return a;
}

#define LDSM4(r, addr) \
    asm volatile("ldmatrix.sync.aligned.m8n8.x4.shared.b16 {%0,%1,%2,%3}, [%4];" \
        : "=r"((r)[0]), "=r"((r)[1]), "=r"((r)[2]), "=r"((r)[3]) : "r"(addr))

#define MMA_F16(d, a, b) \
    asm volatile("mma.sync.aligned.m16n8k16.row.col.f32.f16.f16.f32 " \
        "{%0,%1,%2,%3}, {%4,%5,%6,%7}, {%8,%9}, {%0,%1,%2,%3};" \
        : "+f"((d)[0]), "+f"((d)[1]), "+f"((d)[2]), "+f"((d)[3]) \
        : "r"((a)[0]), "r"((a)[1]), "r"((a)[2]), "r"((a)[3]), \
          "r"((b)[0]), "r"((b)[1]))

__device__ __forceinline__ bool edges_is64(const int* E) {
    return (E[1] == 0) && (E[3] == 0) && (E[5] == 0) && (E[7] == 0);
}

__device__ __forceinline__ float4 h4_to_f4(uint2 u) {
    const float2 a = __half22float2(*(__half2*)&u.x);
    const float2 b = __half22float2(*(__half2*)&u.y);
    return make_float4(a.x, a.y, b.x, b.y);
}
__device__ __forceinline__ uint2 f4_to_h4(float4 v) {
    uint2 u;
    __half2 a = __floats2half2_rn(v.x, v.y);
    __half2 b = __floats2half2_rn(v.z, v.w);
    u.x = *(uint32_t*)&a; u.y = *(uint32_t*)&b;
    return u;
}
#define F4ADD(a, b) { (a).x += (b).x; (a).y += (b).y; (a).z += (b).z; (a).w += (b).w; }

// ---------------------------------------------------------------------------
// one-time converts, single launch:
//   x -> fp16, 5x W -> fp16 ([n][k]), zero g_cnt
// ---------------------------------------------------------------------------
struct WPtrs { const float* w[5]; };

__global__ void cvt_all_kernel(const float* __restrict__ X, __half* __restrict__ O,
                               WPtrs p, __half* __restrict__ HI) {
    const int i = blockIdx.x * blockDim.x + threadIdx.x;
    if (i < NNODES * 32)
        ((uint2*)O)[i] = f4_to_h4(((const float4*)X)[i]);
    if (i < NNODES) g_cnt[i] = 0;
    if (i < 5 * 16384) {
        const int s = i >> 14;
        const int idx = i & 16383;
        const int n = idx & 127, k = idx >> 7;
        HI[s * 16384 + n * 128 + k] = __float2half_rn(p.w[s][k * 128 + n]);
    }
}

// ---------------------------------------------------------------------------
// CSR build: histogram -> 2-kernel scan -> scatter
// ---------------------------------------------------------------------------
__global__ void hist_kernel(const int* __restrict__ E) {
    int e = blockIdx.x * blockDim.x + threadIdx.x;
    if (e >= NEDGES) return;
    const int dst = edges_is64(E) ? E[2 * (NEDGES + e)] : E[NEDGES + e];
    atomicAdd(&g_cnt[dst], 1);
}

__global__ void scan1_kernel() {
    __shared__ int wsum[32];
    const int tid = threadIdx.x;
    const int idx = blockIdx.x * 1024 + tid;
    int v = (idx < NNODES) ? g_cnt[idx] : 0;
    #pragma unroll
    for (int o = 16; o; o >>= 1) v += __shfl_down_sync(0xffffffffu, v, o);
    if ((tid & 31) == 0) wsum[tid >> 5] = v;
    __syncthreads();
    if (tid < 32) {
        int s = wsum[tid];
        #pragma unroll
        for (int o = 16; o; o >>= 1) s += __shfl_down_sync(0xffffffffu, s, o);
        if (tid == 0) g_bsum[blockIdx.x] = s;
    }
}

__global__ void scan2_kernel() {
    __shared__ int s[1024];
    __shared__ int sbase;
    const int tid = threadIdx.x;
    const int b = blockIdx.x;
    const int idx = b * 1024 + tid;
    const int c = (idx < NNODES) ? g_cnt[idx] : 0;
    s[tid] = c;
    if (tid < 32) {
        int acc = 0;
        for (int j = tid; j < b; j += 32) acc += g_bsum[j];
        #pragma unroll
        for (int o = 16; o; o >>= 1) acc += __shfl_down_sync(0xffffffffu, acc, o);
        if (tid == 0) sbase = acc;
    }
    __syncthreads();
    for (int o = 1; o < 1024; o <<= 1) {
        int t = (tid >= o) ? s[tid - o] : 0;
        __syncthreads();
        s[tid] += t;
        __syncthreads();
    }
    if (idx < NNODES) {
        const int excl = sbase + s[tid] - c;
        g_off[idx] = excl;
        g_cnt[idx] = excl;
    }
    if (b == 0 && tid == 0) g_off[NNODES] = NEDGES;
}

__global__ void scatter_kernel(const int* __restrict__ E) {
    int e = blockIdx.x * blockDim.x + threadIdx.x;
    if (e >= NEDGES) return;
    int src, dst;
    if (edges_is64(E)) { src = E[2 * e]; dst = E[2 * (NEDGES + e)]; }
    else               { src = E[e];     dst = E[NEDGES + e]; }
    const int pos = atomicAdd(&g_cnt[dst], 1);
    g_srcs[pos] = src;
}

// ---------------------------------------------------------------------------
// Standalone aggregation (warp per node, MLP=4, lean registers, high occ):
//   A[i] = (1+eps)*X[i] + sum_{j->i} X[j]
// ---------------------------------------------------------------------------
__global__ void agg_kernel(const __half* __restrict__ X,
                           const float* __restrict__ eps,
                           __half* __restrict__ A) {
    const int node = blockIdx.x * 8 + (threadIdx.x >> 5);
    if (node >= NNODES) return;
    const int lane = threadIdx.x & 31;
    const float s = 1.0f + *eps;
    const uint2* X2 = (const uint2*)X;

    const float4 a = h4_to_f4(X2[(size_t)node * 32 + lane]);
    float4 acc0 = make_float4(a.x * s, a.y * s, a.z * s, a.w * s);
    float4 acc1 = make_float4(0.f, 0.f, 0.f, 0.f);
    float4 acc2 = make_float4(0.f, 0.f, 0.f, 0.f);
    float4 acc3 = make_float4(0.f, 0.f, 0.f, 0.f);

    const int end = g_off[node + 1];
    int j = g_off[node];
    for (; j + 3 < end; j += 4) {
        const int s0 = g_srcs[j],     s1 = g_srcs[j + 1];
        const int s2 = g_srcs[j + 2], s3 = g_srcs[j + 3];
        const float4 v0 = h4_to_f4(X2[(size_t)s0 * 32 + lane]);
        const float4 v1 = h4_to_f4(X2[(size_t)s1 * 32 + lane]);
        const float4 v2 = h4_to_f4(X2[(size_t)s2 * 32 + lane]);
        const float4 v3 = h4_to_f4(X2[(size_t)s3 * 32 + lane]);
        F4ADD(acc0, v0); F4ADD(acc1, v1);
        F4ADD(acc2, v2); F4ADD(acc3, v3);
    }
    for (; j < end; j++) {
        const float4 v0 = h4_to_f4(X2[(size_t)g_srcs[j] * 32 + lane]);
        F4ADD(acc0, v0);
    }
    F4ADD(acc2, acc3);
    F4ADD(acc0, acc1);
    F4ADD(acc0, acc2);
    ((uint2*)A)[(size_t)node * 32 + lane] = f4_to_h4(acc0);
}

// ---------------------------------------------------------------------------
// GEMM smem layout (single-fp16 weights)
// ---------------------------------------------------------------------------
#define STRIDE  272
#define SA      0
#define SB_HI   17408
#define SM_BIAS 52224
#define SM_TOT  52736

// ---- common GEMM body: B fill, software-pipelined mainloop, epilogue ----
__device__ __forceinline__ void gemm_body(
    char* smem, const __half* __restrict__ WH,
    const float* __restrict__ bias, __half* __restrict__ Y,
    int tid, int wid, int lane, int base)
{
    if (tid < 128) *(float*)(smem + SM_BIAS + tid * 4) = bias[tid];

    // B tile: pure fp16 copy (preconverted, [n][k] layout)
    {
        const uint4* WH4 = (const uint4*)WH;
        #pragma unroll
        for (int idx = tid; idx < 2048; idx += 256) {
            const int n = idx >> 4, g = idx & 15;
            *(uint4*)(smem + SB_HI + n * STRIDE + g * 16) = WH4[idx];
        }
    }
    __syncthreads();

    const uint32_t sb = smem_u32(smem);
    const int wr = wid & 3;       // 16-row group
    const int wc = wid >> 2;      // 64-col half

    const uint32_t a_base = sb + (uint32_t)((wr * 16 + (lane & 15)) * STRIDE
                                            + ((lane >> 4) << 4));
    const uint32_t b_base = sb + SB_HI +
        (uint32_t)((wc * 64 + (lane & 7) + ((lane & 16) ? 8 : 0)) * STRIDE
                   + ((lane & 8) ? 16 : 0));

    float acc[8][4];
    #pragma unroll
    for (int n = 0; n < 8; n++)
        #pragma unroll
        for (int j = 0; j < 4; j++) acc[n][j] = 0.f;

    // double-buffered fragment registers
    uint32_t ah[2][4], bh[2][8][2];

    LDSM4(ah[0], a_base);
    #pragma unroll
    for (int u = 0; u < 4; u++) {
        uint32_t r[4];
        LDSM4(r, b_base + u * 16 * STRIDE);
        bh[0][2 * u][0] = r[0]; bh[0][2 * u][1] = r[1];
        bh[0][2 * u + 1][0] = r[2]; bh[0][2 * u + 1][1] = r[3];
    }

    #pragma unroll
    for (int ks = 0; ks < 8; ks++) {
        const int cur = ks & 1, nxt = cur ^ 1;
        if (ks < 7) {
            const uint32_t kb = (ks + 1) * 32;
            LDSM4(ah[nxt], a_base + kb);
            #pragma unroll
            for (int u = 0; u < 4; u++) {
                uint32_t r[4];
                LDSM4(r, b_base + u * 16 * STRIDE + kb);
                bh[nxt][2 * u][0] = r[0]; bh[nxt][2 * u][1] = r[1];
                bh[nxt][2 * u + 1][0] = r[2]; bh[nxt][2 * u + 1][1] = r[3];
            }
        }
        #pragma unroll
        for (int n = 0; n < 8; n++)
            MMA_F16(acc[n], ah[cur], bh[cur][n]);
    }

    // epilogue: bias + relu, store fp16
    const float* sBias = (const float*)(smem + SM_BIAS);
    const int r0 = base + wr * 16 + (lane >> 2);
    #pragma unroll
    for (int n = 0; n < 8; n++) {
        const int col = wc * 64 + n * 8 + 2 * (lane & 3);
        const float b0 = sBias[col], b1 = sBias[col + 1];
        const float v0 = fmaxf(acc[n][0] + b0, 0.f);
        const float v1 = fmaxf(acc[n][1] + b1, 0.f);
        const float v2 = fmaxf(acc[n][2] + b0, 0.f);
        const float v3 = fmaxf(acc[n][3] + b1, 0.f);
        if (r0 < NNODES) {
            const __half2 h = __floats2half2_rn(v0, v1);
            *(uint32_t*)(Y + (size_t)r0 * 128 + col) = *(const uint32_t*)&h;
        }
        if (r0 + 8 < NNODES) {
            const __half2 h = __floats2half2_rn(v2, v3);
            *(uint32_t*)(Y + (size_t)(r0 + 8) * 128 + col) = *(const uint32_t*)&h;
        }
    }
}

// ---------------------------------------------------------------------------
// Plain GEMM: A tile = straight fp16 row copy
// ---------------------------------------------------------------------------
__global__ void __launch_bounds__(256, 2)
mma_gemm_kernel(const __half* __restrict__ X,
                const __half* __restrict__ WH,
                const float* __restrict__ bias, __half* __restrict__ Y) {
    extern __shared__ char smem[];
    const int tid = threadIdx.x;
    const int wid = tid >> 5;
    const int lane = tid & 31;
    const int base = blockIdx.x * 64;

    {
        const uint4* X16 = (const uint4*)X;
        #pragma unroll
        for (int idx = tid; idx < 1024; idx += 256) {
            const int rl = idx >> 4, g = idx & 15;
            const int row = base + rl;
            uint4 v = make_uint4(0u, 0u, 0u, 0u);
            if (row < NNODES) v = X16[(size_t)row * 16 + g];
            *(uint4*)(smem + SA + rl * STRIDE + g * 16) = v;
        }
    }
    gemm_body(smem, WH, bias, Y, tid, wid, lane, base);
}

// ---------------------------------------------------------------------------
// Final layer: out = log_softmax(X(fp16) @ W[128,40] + b)
// ---------------------------------------------------------------------------
#define G40_SMEM ((128 * 40 + 64 * 128 + 64 * 40 + 64) * 4)   // 63744

__global__ void gemm40_softmax_kernel(const __half* __restrict__ X,
                                      const float* __restrict__ W,
                                      const float* __restrict__ bias,
                                      float* __restrict__ out) {
    extern __shared__ float fsm[];
    float* sW = fsm;                       // 128*40
    float* sX = fsm + 128 * 40;            // 64*128
    float* sOut = sX + 64 * 128;           // 64*40
    float* sLs = sOut + 64 * 40;           // 64

    const int tid = threadIdx.x;
    const int base = blockIdx.x * 64;

    float4* sW4 = (float4*)sW;
    const float4* W4 = (const float4*)W;
    #pragma unroll 4
    for (int i = tid; i < 128 * 10; i += 80) sW4[i] = W4[i];

    float4* sX4 = (float4*)sX;
    const uint2* X2 = (const uint2*)X;
    #pragma unroll 4
    for (int i = tid; i < 64 * 32; i += 80) {
        const int rl = i >> 5;
        const int row = base + rl;
        sX4[i] = (row < NNODES) ? h4_to_f4(X2[(size_t)row * 32 + (i & 31)])
                                : make_float4(0.f, 0.f, 0.f, 0.f);
    }
    __syncthreads();

    const int cg = tid % 5;
    const int rg = tid / 5;

    float acc[4][8];
    #pragma unroll
    for (int r = 0; r < 4; r++)
        #pragma unroll
        for (int j = 0; j < 8; j++) acc[r][j] = 0.f;

    #pragma unroll 2
    for (int k0 = 0; k0 < 128; k0 += 4) {
        float4 xv[4];
        #pragma unroll
        for (int r = 0; r < 4; r++)
            xv[r] = sX4[(rg * 4 + r) * 32 + (k0 >> 2)];
        #pragma unroll
        for (int j = 0; j < 4; j++) {
            const float4 wa = sW4[(k0 + j) * 10 + cg * 2];
            const float4 wb = sW4[(k0 + j) * 10 + cg * 2 + 1];
            #pragma unroll
            for (int r = 0; r < 4; r++) {
                const float xs = (j == 0) ? xv[r].x :
                                 (j == 1) ? xv[r].y :
                                 (j == 2) ? xv[r].z : xv[r].w;
                acc[r][0] = fmaf(xs, wa.x, acc[r][0]);
                acc[r][1] = fmaf(xs, wa.y, acc[r][1]);
                acc[r][2] = fmaf(xs, wa.z, acc[r][2]);
                acc[r][3] = fmaf(xs, wa.w, acc[r][3]);
                acc[r][4] = fmaf(xs, wb.x, acc[r][4]);
                acc[r][5] = fmaf(xs, wb.y, acc[r][5]);
                acc[r][6] = fmaf(xs, wb.z, acc[r][6]);
                acc[r][7] = fmaf(xs, wb.w, acc[r][7]);
            }
        }
    }

    float bb[8];
    #pragma unroll
    for (int j = 0; j < 8; j++) bb[j] = bias[cg * 8 + j];

    #pragma unroll
    for (int r = 0; r < 4; r++) {
        const int rl = rg * 4 + r;
        float4 v0 = make_float4(acc[r][0] + bb[0], acc[r][1] + bb[1],
                                acc[r][2] + bb[2], acc[r][3] + bb[3]);
        float4 v1 = make_float4(acc[r][4] + bb[4], acc[r][5] + bb[5],
                                acc[r][6] + bb[6], acc[r][7] + bb[7]);
        *(float4*)(sOut + rl * 40 + cg * 8) = v0;
        *(float4*)(sOut + rl * 40 + cg * 8 + 4) = v1;
    }
    __syncthreads();

    if (tid < 64 && base + tid < NNODES) {
        const float* p = sOut + tid * 40;
        float m = p[0];
        #pragma unroll 8
        for (int c = 1; c < 40; c++) m = fmaxf(m, p[c]);
        float s = 0.f;
        #pragma unroll 8
        for (int c = 0; c < 40; c++) s += expf(p[c] - m);
        sLs[tid] = m + logf(s);
    }
    __syncthreads();

    #pragma unroll
    for (int r = 0; r < 4; r++) {
        const int rl = rg * 4 + r;
        const int row = base + rl;
        if (row < NNODES) {
            const float ls = sLs[rl];
            float4 v0 = make_float4(acc[r][0] + bb[0] - ls, acc[r][1] + bb[1] - ls,
                                    acc[r][2] + bb[2] - ls, acc[r][3] + bb[3] - ls);
            float4 v1 = make_float4(acc[r][4] + bb[4] - ls, acc[r][5] + bb[5] - ls,
                                    acc[r][6] + bb[6] - ls, acc[r][7] + bb[7] - ls);
            float4* o = (float4*)(out + (size_t)row * 40 + cg * 8);
            o[0] = v0;
            o[1] = v1;
        }
    }
}

// ---------------------------------------------------------------------------
extern "C" void kernel_launch(void* const* d_in, const int* in_sizes, int n_in,
                              void* d_out, int out_size) {
    const float* x     = (const float*)d_in[0];
    const int*   edges = (const int*)d_in[1];
    const float* W1[3] = {(const float*)d_in[2], (const float*)d_in[7],  (const float*)d_in[12]};
    const float* b1[3] = {(const float*)d_in[3], (const float*)d_in[8],  (const float*)d_in[13]};
    const float* W2[3] = {(const float*)d_in[4], (const float*)d_in[9],  (const float*)d_in[14]};
    const float* b2[3] = {(const float*)d_in[5], (const float*)d_in[10], (const float*)d_in[15]};
    const float* ep[3] = {(const float*)d_in[6], (const float*)d_in[11], (const float*)d_in[16]};
    float* out = (float*)d_out;

    void *ph, *py, *pa, *phi;
    cudaGetSymbolAddress(&ph, g_h);
    cudaGetSymbolAddress(&py, g_y);
    cudaGetSymbolAddress(&pa, g_aggr);
    cudaGetSymbolAddress(&phi, g_whi);
    __half* h    = (__half*)ph;
    __half* y    = (__half*)py;    // also holds x16 until layer-0 GEMM2
    __half* aggr = (__half*)pa;
    __half* whi  = (__half*)phi;

    cudaFuncSetAttribute(mma_gemm_kernel,
                         cudaFuncAttributeMaxDynamicSharedMemorySize, SM_TOT);
    cudaFuncSetAttribute(gemm40_softmax_kernel,
                         cudaFuncAttributeMaxDynamicSharedMemorySize, G40_SMEM);

    const int edge_blocks = (NEDGES + 255) / 256;           // 6250
    const int scan_blocks = (NNODES + 1023) / 1024;         // 98
    const int agg_blocks  = (NNODES + 7) / 8;               // 12500
    const int mm_blocks   = (NNODES + 63) / 64;             // 1563

    // ---- one-time converts (single launch) + CSR build ----
    WPtrs wp; wp.w[0] = W1[0]; wp.w[1] = W2[0]; wp.w[2] = W1[1];
    wp.w[3] = W2[1]; wp.w[4] = W1[2];
    cvt_all_kernel<<<(NNODES * 32 + 255) / 256, 256>>>(x, y, wp, whi);
    hist_kernel<<<edge_blocks, 256>>>(edges);
    scan1_kernel<<<scan_blocks, 1024>>>();
    scan2_kernel<<<scan_blocks, 1024>>>();
    scatter_kernel<<<edge_blocks, 256>>>(edges);

    // ---- layer 0 ----  (y currently holds x16)
    agg_kernel<<<agg_blocks, 256>>>(y, ep[0], aggr);
    mma_gemm_kernel<<<mm_blocks, 256, SM_TOT>>>(aggr, whi + 0 * 16384, b1[0], h);
    mma_gemm_kernel<<<mm_blocks, 256, SM_TOT>>>(h, whi + 1 * 16384, b2[0], y);
    // ---- layer 1 ----
    agg_kernel<<<agg_blocks, 256>>>(y, ep[1], aggr);
    mma_gemm_kernel<<<mm_blocks, 256, SM_TOT>>>(aggr, whi + 2 * 16384, b1[1], h);
    mma_gemm_kernel<<<mm_blocks, 256, SM_TOT>>>(h, whi + 3 * 16384, b2[1], y);
    // ---- layer 2 ----
    agg_kernel<<<agg_blocks, 256>>>(y, ep[2], aggr);
    mma_gemm_kernel<<<mm_blocks, 256, SM_TOT>>>(aggr, whi + 4 * 16384, b1[2], h);
    gemm40_softmax_kernel<<<mm_blocks, 80, G40_SMEM>>>(h, W2[2], b2[2], out);

    (void)in_sizes; (void)n_in; (void)out_size;
}

// round 15
// speedup vs baseline: 1.5587x; 1.0583x over previous
#include <cuda_runtime.h>
#include <cuda_fp16.h>
#include <math.h>
#include <cstdint>

#define NNODES 100000
#define NEDGES 1600000
#define D 128

// Scratch (allocation-free: __device__ globals)
__device__ __align__(16) __half g_h[NNODES * D];
__device__ __align__(16) __half g_y[NNODES * D];
__device__ __align__(16) __half g_aggr[NNODES * D];
__device__ __align__(16) __half g_whi[5 * 128 * 128];
__device__ int g_cnt[NNODES];
__device__ int g_off[NNODES + 1];
__device__ int g_bsum[128];
__device__ int g_srcs[NEDGES];

// ---------------------------------------------------------------------------
// helpers
// ---------------------------------------------------------------------------
__device__ __forceinline__ uint32_t smem_u32(const void* p) {
    uint32_t a;
    asm("{ .reg .u64 t; cvta.to.shared.u64 t, %1; cvt.u32.u64 %0, t; }"
        : "=r"(a) : "l"(p));
    return a;
}

#define LDSM4(r, addr) \
    asm volatile("ldmatrix.sync.aligned.m8n8.x4.shared.b16 {%0,%1,%2,%3}, [%4];" \
        : "=r"((r)[0]), "=r"((r)[1]), "=r"((r)[2]), "=r"((r)[3]) : "r"(addr))

#define MMA_F16(d, a, b) \
    asm volatile("mma.sync.aligned.m16n8k16.row.col.f32.f16.f16.f32 " \
        "{%0,%1,%2,%3}, {%4,%5,%6,%7}, {%8,%9}, {%0,%1,%2,%3};" \
        : "+f"((d)[0]), "+f"((d)[1]), "+f"((d)[2]), "+f"((d)[3]) \
        : "r"((a)[0]), "r"((a)[1]), "r"((a)[2]), "r"((a)[3]), \
          "r"((b)[0]), "r"((b)[1]))

__device__ __forceinline__ bool edges_is64(const int* E) {
    return (E[1] == 0) && (E[3] == 0) && (E[5] == 0) && (E[7] == 0);
}

__device__ __forceinline__ float4 h4_to_f4(uint2 u) {
    const float2 a = __half22float2(*(__half2*)&u.x);
    const float2 b = __half22float2(*(__half2*)&u.y);
    return make_float4(a.x, a.y, b.x, b.y);
}
__device__ __forceinline__ uint2 f4_to_h4(float4 v) {
    uint2 u;
    __half2 a = __floats2half2_rn(v.x, v.y);
    __half2 b = __floats2half2_rn(v.z, v.w);
    u.x = *(uint32_t*)&a; u.y = *(uint32_t*)&b;
    return u;
}
#define F4ADD(a, b) { (a).x += (b).x; (a).y += (b).y; (a).z += (b).z; (a).w += (b).w; }

// ---------------------------------------------------------------------------
// one-time converts, single launch
// ---------------------------------------------------------------------------
struct WPtrs { const float* w[5]; };

__global__ void cvt_all_kernel(const float* __restrict__ X, __half* __restrict__ O,
                               WPtrs p, __half* __restrict__ HI) {
    const int i = blockIdx.x * blockDim.x + threadIdx.x;
    if (i < NNODES * 32)
        ((uint2*)O)[i] = f4_to_h4(((const float4*)X)[i]);
    if (i < NNODES) g_cnt[i] = 0;
    if (i < 5 * 16384) {
        const int s = i >> 14;
        const int idx = i & 16383;
        const int n = idx & 127, k = idx >> 7;
        HI[s * 16384 + n * 128 + k] = __float2half_rn(p.w[s][k * 128 + n]);
    }
}

// ---------------------------------------------------------------------------
// CSR build: histogram -> 2-kernel scan -> scatter
// ---------------------------------------------------------------------------
__global__ void hist_kernel(const int* __restrict__ E) {
    int e = blockIdx.x * blockDim.x + threadIdx.x;
    if (e >= NEDGES) return;
    const int dst = edges_is64(E) ? E[2 * (NEDGES + e)] : E[NEDGES + e];
    atomicAdd(&g_cnt[dst], 1);
}

__global__ void scan1_kernel() {
    __shared__ int wsum[32];
    const int tid = threadIdx.x;
    const int idx = blockIdx.x * 1024 + tid;
    int v = (idx < NNODES) ? g_cnt[idx] : 0;
    #pragma unroll
    for (int o = 16; o; o >>= 1) v += __shfl_down_sync(0xffffffffu, v, o);
    if ((tid & 31) == 0) wsum[tid >> 5] = v;
    __syncthreads();
    if (tid < 32) {
        int s = wsum[tid];
        #pragma unroll
        for (int o = 16; o; o >>= 1) s += __shfl_down_sync(0xffffffffu, s, o);
        if (tid == 0) g_bsum[blockIdx.x] = s;
    }
}

__global__ void scan2_kernel() {
    __shared__ int s[1024];
    __shared__ int sbase;
    const int tid = threadIdx.x;
    const int b = blockIdx.x;
    const int idx = b * 1024 + tid;
    const int c = (idx < NNODES) ? g_cnt[idx] : 0;
    s[tid] = c;
    if (tid < 32) {
        int acc = 0;
        for (int j = tid; j < b; j += 32) acc += g_bsum[j];
        #pragma unroll
        for (int o = 16; o; o >>= 1) acc += __shfl_down_sync(0xffffffffu, acc, o);
        if (tid == 0) sbase = acc;
    }
    __syncthreads();
    for (int o = 1; o < 1024; o <<= 1) {
        int t = (tid >= o) ? s[tid - o] : 0;
        __syncthreads();
        s[tid] += t;
        __syncthreads();
    }
    if (idx < NNODES) {
        const int excl = sbase + s[tid] - c;
        g_off[idx] = excl;
        g_cnt[idx] = excl;
    }
    if (b == 0 && tid == 0) g_off[NNODES] = NEDGES;
}

__global__ void scatter_kernel(const int* __restrict__ E) {
    int e = blockIdx.x * blockDim.x + threadIdx.x;
    if (e >= NEDGES) return;
    int src, dst;
    if (edges_is64(E)) { src = E[2 * e]; dst = E[2 * (NEDGES + e)]; }
    else               { src = E[e];     dst = E[NEDGES + e]; }
    const int pos = atomicAdd(&g_cnt[dst], 1);
    g_srcs[pos] = src;
}

// ---------------------------------------------------------------------------
// Standalone aggregation (warp per node, MLP=4, lean registers, high occ)
// ---------------------------------------------------------------------------
__global__ void agg_kernel(const __half* __restrict__ X,
                           const float* __restrict__ eps,
                           __half* __restrict__ A) {
    const int node = blockIdx.x * 8 + (threadIdx.x >> 5);
    if (node >= NNODES) return;
    const int lane = threadIdx.x & 31;
    const float s = 1.0f + *eps;
    const uint2* X2 = (const uint2*)X;

    const float4 a = h4_to_f4(X2[(size_t)node * 32 + lane]);
    float4 acc0 = make_float4(a.x * s, a.y * s, a.z * s, a.w * s);
    float4 acc1 = make_float4(0.f, 0.f, 0.f, 0.f);
    float4 acc2 = make_float4(0.f, 0.f, 0.f, 0.f);
    float4 acc3 = make_float4(0.f, 0.f, 0.f, 0.f);

    const int end = g_off[node + 1];
    int j = g_off[node];
    for (; j + 3 < end; j += 4) {
        const int s0 = g_srcs[j],     s1 = g_srcs[j + 1];
        const int s2 = g_srcs[j + 2], s3 = g_srcs[j + 3];
        const float4 v0 = h4_to_f4(X2[(size_t)s0 * 32 + lane]);
        const float4 v1 = h4_to_f4(X2[(size_t)s1 * 32 + lane]);
        const float4 v2 = h4_to_f4(X2[(size_t)s2 * 32 + lane]);
        const float4 v3 = h4_to_f4(X2[(size_t)s3 * 32 + lane]);
        F4ADD(acc0, v0); F4ADD(acc1, v1);
        F4ADD(acc2, v2); F4ADD(acc3, v3);
    }
    for (; j < end; j++) {
        const float4 v0 = h4_to_f4(X2[(size_t)g_srcs[j] * 32 + lane]);
        F4ADD(acc0, v0);
    }
    F4ADD(acc2, acc3);
    F4ADD(acc0, acc1);
    F4ADD(acc0, acc2);
    ((uint2*)A)[(size_t)node * 32 + lane] = f4_to_h4(acc0);
}

// ---------------------------------------------------------------------------
// GEMM smem layouts
// ---------------------------------------------------------------------------
#define STRIDE  272
#define SA      0
#define SB_HI   17408
#define SM_BIAS 52224
#define SM_TOT  52736
// fused two-GEMM layout
#define F_SB2   52224
#define F_B1    87040
#define F_B2    87552
#define F_TOT   88064

// ---- pipelined MMA mainloop over K=128: acc += A_tile @ B_tile^T ----
__device__ __forceinline__ void mma_mainloop(uint32_t a_base, uint32_t b_base,
                                             float acc[8][4]) {
    uint32_t ah[2][4], bh[2][8][2];
    LDSM4(ah[0], a_base);
    #pragma unroll
    for (int u = 0; u < 4; u++) {
        uint32_t r[4];
        LDSM4(r, b_base + u * 16 * STRIDE);
        bh[0][2 * u][0] = r[0]; bh[0][2 * u][1] = r[1];
        bh[0][2 * u + 1][0] = r[2]; bh[0][2 * u + 1][1] = r[3];
    }
    #pragma unroll
    for (int ks = 0; ks < 8; ks++) {
        const int cur = ks & 1, nxt = cur ^ 1;
        if (ks < 7) {
            const uint32_t kb = (ks + 1) * 32;
            LDSM4(ah[nxt], a_base + kb);
            #pragma unroll
            for (int u = 0; u < 4; u++) {
                uint32_t r[4];
                LDSM4(r, b_base + u * 16 * STRIDE + kb);
                bh[nxt][2 * u][0] = r[0]; bh[nxt][2 * u][1] = r[1];
                bh[nxt][2 * u + 1][0] = r[2]; bh[nxt][2 * u + 1][1] = r[3];
            }
        }
        #pragma unroll
        for (int n = 0; n < 8; n++)
            MMA_F16(acc[n], ah[cur], bh[cur][n]);
    }
}

// ---------------------------------------------------------------------------
// Fused per-layer MLP: Y = relu(relu(A@W1+b1)@W2+b2), A tile from global.
// H staged in smem A-slot between the two mainloops.
// ---------------------------------------------------------------------------
__global__ void __launch_bounds__(256, 2)
fused_mlp_kernel(const __half* __restrict__ X,
                 const __half* __restrict__ WH1, const float* __restrict__ b1,
                 const __half* __restrict__ WH2, const float* __restrict__ b2,
                 __half* __restrict__ Y) {
    extern __shared__ char smem[];
    const int tid = threadIdx.x;
    const int wid = tid >> 5;
    const int lane = tid & 31;
    const int base = blockIdx.x * 64;

    if (tid < 128) *(float*)(smem + F_B1 + tid * 4) = b1[tid];
    else           *(float*)(smem + F_B2 + (tid - 128) * 4) = b2[tid - 128];

    // A tile: straight fp16 row copy
    {
        const uint4* X16 = (const uint4*)X;
        #pragma unroll
        for (int idx = tid; idx < 1024; idx += 256) {
            const int rl = idx >> 4, g = idx & 15;
            const int row = base + rl;
            uint4 v = make_uint4(0u, 0u, 0u, 0u);
            if (row < NNODES) v = X16[(size_t)row * 16 + g];
            *(uint4*)(smem + SA + rl * STRIDE + g * 16) = v;
        }
    }
    // B tiles for both GEMMs
    {
        const uint4* W14 = (const uint4*)WH1;
        const uint4* W24 = (const uint4*)WH2;
        #pragma unroll
        for (int idx = tid; idx < 2048; idx += 256) {
            const int n = idx >> 4, g = idx & 15;
            *(uint4*)(smem + SB_HI + n * STRIDE + g * 16) = W14[idx];
            *(uint4*)(smem + F_SB2 + n * STRIDE + g * 16) = W24[idx];
        }
    }
    __syncthreads();

    const uint32_t sb = smem_u32(smem);
    const int wr = wid & 3;       // 16-row group
    const int wc = wid >> 2;      // 64-col half
    const uint32_t a_base = sb + (uint32_t)((wr * 16 + (lane & 15)) * STRIDE
                                            + ((lane >> 4) << 4));
    const uint32_t b_off = (uint32_t)((wc * 64 + (lane & 7) + ((lane & 16) ? 8 : 0)) * STRIDE
                                      + ((lane & 8) ? 16 : 0));

    float acc[8][4];
    #pragma unroll
    for (int n = 0; n < 8; n++)
        #pragma unroll
        for (int j = 0; j < 4; j++) acc[n][j] = 0.f;

    // ---- GEMM 1 ----
    mma_mainloop(a_base, sb + SB_HI + b_off, acc);

    __syncthreads();   // all warps done reading A before H overwrites it

    // H = relu(acc + b1) -> smem A-slot (fp16, same layout)
    {
        const float* sB1 = (const float*)(smem + F_B1);
        const int rl0 = wr * 16 + (lane >> 2);
        #pragma unroll
        for (int n = 0; n < 8; n++) {
            const int col = wc * 64 + n * 8 + 2 * (lane & 3);
            const float c0 = sB1[col], c1 = sB1[col + 1];
            const __half2 h0 = __floats2half2_rn(fmaxf(acc[n][0] + c0, 0.f),
                                                 fmaxf(acc[n][1] + c1, 0.f));
            const __half2 h1 = __floats2half2_rn(fmaxf(acc[n][2] + c0, 0.f),
                                                 fmaxf(acc[n][3] + c1, 0.f));
            *(uint32_t*)(smem + SA + rl0 * STRIDE + col * 2) = *(const uint32_t*)&h0;
            *(uint32_t*)(smem + SA + (rl0 + 8) * STRIDE + col * 2) = *(const uint32_t*)&h1;
        }
    }
    __syncthreads();

    #pragma unroll
    for (int n = 0; n < 8; n++)
        #pragma unroll
        for (int j = 0; j < 4; j++) acc[n][j] = 0.f;

    // ---- GEMM 2 ----
    mma_mainloop(a_base, sb + F_SB2 + b_off, acc);

    // epilogue: bias2 + relu -> global fp16
    {
        const float* sB2 = (const float*)(smem + F_B2);
        const int r0 = base + wr * 16 + (lane >> 2);
        #pragma unroll
        for (int n = 0; n < 8; n++) {
            const int col = wc * 64 + n * 8 + 2 * (lane & 3);
            const float c0 = sB2[col], c1 = sB2[col + 1];
            const float v0 = fmaxf(acc[n][0] + c0, 0.f);
            const float v1 = fmaxf(acc[n][1] + c1, 0.f);
            const float v2 = fmaxf(acc[n][2] + c0, 0.f);
            const float v3 = fmaxf(acc[n][3] + c1, 0.f);
            if (r0 < NNODES) {
                const __half2 h = __floats2half2_rn(v0, v1);
                *(uint32_t*)(Y + (size_t)r0 * 128 + col) = *(const uint32_t*)&h;
            }
            if (r0 + 8 < NNODES) {
                const __half2 h = __floats2half2_rn(v2, v3);
                *(uint32_t*)(Y + (size_t)(r0 + 8) * 128 + col) = *(const uint32_t*)&h;
            }
        }
    }
}

// ---------------------------------------------------------------------------
// Single GEMM (layer 2 first half): Y = relu(X@W+b)
// ---------------------------------------------------------------------------
__global__ void __launch_bounds__(256, 2)
mma_gemm_kernel(const __half* __restrict__ X,
                const __half* __restrict__ WH,
                const float* __restrict__ bias, __half* __restrict__ Y) {
    extern __shared__ char smem[];
    const int tid = threadIdx.x;
    const int wid = tid >> 5;
    const int lane = tid & 31;
    const int base = blockIdx.x * 64;

    if (tid < 128) *(float*)(smem + SM_BIAS + tid * 4) = bias[tid];
    {
        const uint4* X16 = (const uint4*)X;
        #pragma unroll
        for (int idx = tid; idx < 1024; idx += 256) {
            const int rl = idx >> 4, g = idx & 15;
            const int row = base + rl;
            uint4 v = make_uint4(0u, 0u, 0u, 0u);
            if (row < NNODES) v = X16[(size_t)row * 16 + g];
            *(uint4*)(smem + SA + rl * STRIDE + g * 16) = v;
        }
    }
    {
        const uint4* WH4 = (const uint4*)WH;
        #pragma unroll
        for (int idx = tid; idx < 2048; idx += 256) {
            const int n = idx >> 4, g = idx & 15;
            *(uint4*)(smem + SB_HI + n * STRIDE + g * 16) = WH4[idx];
        }
    }
    __syncthreads();

    const uint32_t sb = smem_u32(smem);
    const int wr = wid & 3;
    const int wc = wid >> 2;
    const uint32_t a_base = sb + (uint32_t)((wr * 16 + (lane & 15)) * STRIDE
                                            + ((lane >> 4) << 4));
    const uint32_t b_base = sb + SB_HI +
        (uint32_t)((wc * 64 + (lane & 7) + ((lane & 16) ? 8 : 0)) * STRIDE
                   + ((lane & 8) ? 16 : 0));

    float acc[8][4];
    #pragma unroll
    for (int n = 0; n < 8; n++)
        #pragma unroll
        for (int j = 0; j < 4; j++) acc[n][j] = 0.f;

    mma_mainloop(a_base, b_base, acc);

    const float* sBias = (const float*)(smem + SM_BIAS);
    const int r0 = base + wr * 16 + (lane >> 2);
    #pragma unroll
    for (int n = 0; n < 8; n++) {
        const int col = wc * 64 + n * 8 + 2 * (lane & 3);
        const float b0 = sBias[col], b1 = sBias[col + 1];
        const float v0 = fmaxf(acc[n][0] + b0, 0.f);
        const float v1 = fmaxf(acc[n][1] + b1, 0.f);
        const float v2 = fmaxf(acc[n][2] + b0, 0.f);
        const float v3 = fmaxf(acc[n][3] + b1, 0.f);
        if (r0 < NNODES) {
            const __half2 h = __floats2half2_rn(v0, v1);
            *(uint32_t*)(Y + (size_t)r0 * 128 + col) = *(const uint32_t*)&h;
        }
        if (r0 + 8 < NNODES) {
            const __half2 h = __floats2half2_rn(v2, v3);
            *(uint32_t*)(Y + (size_t)(r0 + 8) * 128 + col) = *(const uint32_t*)&h;
        }
    }
}

// ---------------------------------------------------------------------------
// Final layer: out = log_softmax(X(fp16) @ W[128,40] + b)
// ---------------------------------------------------------------------------
#define G40_SMEM ((128 * 40 + 64 * 128 + 64 * 40 + 64) * 4)   // 63744

__global__ void gemm40_softmax_kernel(const __half* __restrict__ X,
                                      const float* __restrict__ W,
                                      const float* __restrict__ bias,
                                      float* __restrict__ out) {
    extern __shared__ float fsm[];
    float* sW = fsm;                       // 128*40
    float* sX = fsm + 128 * 40;            // 64*128
    float* sOut = sX + 64 * 128;           // 64*40
    float* sLs = sOut + 64 * 40;           // 64

    const int tid = threadIdx.x;
    const int base = blockIdx.x * 64;

    float4* sW4 = (float4*)sW;
    const float4* W4 = (const float4*)W;
    #pragma unroll 4
    for (int i = tid; i < 128 * 10; i += 80) sW4[i] = W4[i];

    float4* sX4 = (float4*)sX;
    const uint2* X2 = (const uint2*)X;
    #pragma unroll 4
    for (int i = tid; i < 64 * 32; i += 80) {
        const int rl = i >> 5;
        const int row = base + rl;
        sX4[i] = (row < NNODES) ? h4_to_f4(X2[(size_t)row * 32 + (i & 31)])
                                : make_float4(0.f, 0.f, 0.f, 0.f);
    }
    __syncthreads();

    const int cg = tid % 5;
    const int rg = tid / 5;

    float acc[4][8];
    #pragma unroll
    for (int r = 0; r < 4; r++)
        #pragma unroll
        for (int j = 0; j < 8; j++) acc[r][j] = 0.f;

    #pragma unroll 2
    for (int k0 = 0; k0 < 128; k0 += 4) {
        float4 xv[4];
        #pragma unroll
        for (int r = 0; r < 4; r++)
            xv[r] = sX4[(rg * 4 + r) * 32 + (k0 >> 2)];
        #pragma unroll
        for (int j = 0; j < 4; j++) {
            const float4 wa = sW4[(k0 + j) * 10 + cg * 2];
            const float4 wb = sW4[(k0 + j) * 10 + cg * 2 + 1];
            #pragma unroll
            for (int r = 0; r < 4; r++) {
                const float xs = (j == 0) ? xv[r].x :
                                 (j == 1) ? xv[r].y :
                                 (j == 2) ? xv[r].z : xv[r].w;
                acc[r][0] = fmaf(xs, wa.x, acc[r][0]);
                acc[r][1] = fmaf(xs, wa.y, acc[r][1]);
                acc[r][2] = fmaf(xs, wa.z, acc[r][2]);
                acc[r][3] = fmaf(xs, wa.w, acc[r][3]);
                acc[r][4] = fmaf(xs, wb.x, acc[r][4]);
                acc[r][5] = fmaf(xs, wb.y, acc[r][5]);
                acc[r][6] = fmaf(xs, wb.z, acc[r][6]);
                acc[r][7] = fmaf(xs, wb.w, acc[r][7]);
            }
        }
    }

    float bb[8];
    #pragma unroll
    for (int j = 0; j < 8; j++) bb[j] = bias[cg * 8 + j];

    #pragma unroll
    for (int r = 0; r < 4; r++) {
        const int rl = rg * 4 + r;
        float4 v0 = make_float4(acc[r][0] + bb[0], acc[r][1] + bb[1],
                                acc[r][2] + bb[2], acc[r][3] + bb[3]);
        float4 v1 = make_float4(acc[r][4] + bb[4], acc[r][5] + bb[5],
                                acc[r][6] + bb[6], acc[r][7] + bb[7]);
        *(float4*)(sOut + rl * 40 + cg * 8) = v0;
        *(float4*)(sOut + rl * 40 + cg * 8 + 4) = v1;
    }
    __syncthreads();

    if (tid < 64 && base + tid < NNODES) {
        const float* p = sOut + tid * 40;
        float m = p[0];
        #pragma unroll 8
        for (int c = 1; c < 40; c++) m = fmaxf(m, p[c]);
        float s = 0.f;
        #pragma unroll 8
        for (int c = 0; c < 40; c++) s += expf(p[c] - m);
        sLs[tid] = m + logf(s);
    }
    __syncthreads();

    #pragma unroll
    for (int r = 0; r < 4; r++) {
        const int rl = rg * 4 + r;
        const int row = base + rl;
        if (row < NNODES) {
            const float ls = sLs[rl];
            float4 v0 = make_float4(acc[r][0] + bb[0] - ls, acc[r][1] + bb[1] - ls,
                                    acc[r][2] + bb[2] - ls, acc[r][3] + bb[3] - ls);
            float4 v1 = make_float4(acc[r][4] + bb[4] - ls, acc[r][5] + bb[5] - ls,
                                    acc[r][6] + bb[6] - ls, acc[r][7] + bb[7] - ls);
            float4* o = (float4*)(out + (size_t)row * 40 + cg * 8);
            o[0] = v0;
            o[1] = v1;
        }
    }
}

// ---------------------------------------------------------------------------
extern "C" void kernel_launch(void* const* d_in, const int* in_sizes, int n_in,
                              void* d_out, int out_size) {
    const float* x     = (const float*)d_in[0];
    const int*   edges = (const int*)d_in[1];
    const float* W1[3] = {(const float*)d_in[2], (const float*)d_in[7],  (const float*)d_in[12]};
    const float* b1[3] = {(const float*)d_in[3], (const float*)d_in[8],  (const float*)d_in[13]};
    const float* W2[3] = {(const float*)d_in[4], (const float*)d_in[9],  (const float*)d_in[14]};
    const float* b2[3] = {(const float*)d_in[5], (const float*)d_in[10], (const float*)d_in[15]};
    const float* ep[3] = {(const float*)d_in[6], (const float*)d_in[11], (const float*)d_in[16]};
    float* out = (float*)d_out;

    void *ph, *py, *pa, *phi;
    cudaGetSymbolAddress(&ph, g_h);
    cudaGetSymbolAddress(&py, g_y);
    cudaGetSymbolAddress(&pa, g_aggr);
    cudaGetSymbolAddress(&phi, g_whi);
    __half* h    = (__half*)ph;
    __half* y    = (__half*)py;    // also holds x16 until layer-0 output overwrite
    __half* aggr = (__half*)pa;
    __half* whi  = (__half*)phi;

    cudaFuncSetAttribute(fused_mlp_kernel,
                         cudaFuncAttributeMaxDynamicSharedMemorySize, F_TOT);
    cudaFuncSetAttribute(mma_gemm_kernel,
                         cudaFuncAttributeMaxDynamicSharedMemorySize, SM_TOT);
    cudaFuncSetAttribute(gemm40_softmax_kernel,
                         cudaFuncAttributeMaxDynamicSharedMemorySize, G40_SMEM);

    const int edge_blocks = (NEDGES + 255) / 256;           // 6250
    const int scan_blocks = (NNODES + 1023) / 1024;         // 98
    const int agg_blocks  = (NNODES + 7) / 8;               // 12500
    const int mm_blocks   = (NNODES + 63) / 64;             // 1563

    // ---- one-time converts (single launch) + CSR build ----
    WPtrs wp; wp.w[0] = W1[0]; wp.w[1] = W2[0]; wp.w[2] = W1[1];
    wp.w[3] = W2[1]; wp.w[4] = W1[2];
    cvt_all_kernel<<<(NNODES * 32 + 255) / 256, 256>>>(x, y, wp, whi);
    hist_kernel<<<edge_blocks, 256>>>(edges);
    scan1_kernel<<<scan_blocks, 1024>>>();
    scan2_kernel<<<scan_blocks, 1024>>>();
    scatter_kernel<<<edge_blocks, 256>>>(edges);

    // ---- layer 0 ----  (y currently holds x16)
    agg_kernel<<<agg_blocks, 256>>>(y, ep[0], aggr);
    fused_mlp_kernel<<<mm_blocks, 256, F_TOT>>>(aggr, whi + 0 * 16384, b1[0],
                                                whi + 1 * 16384, b2[0], y);
    // ---- layer 1 ----
    agg_kernel<<<agg_blocks, 256>>>(y, ep[1], aggr);
    fused_mlp_kernel<<<mm_blocks, 256, F_TOT>>>(aggr, whi + 2 * 16384, b1[1],
                                                whi + 3 * 16384, b2[1], y);
    // ---- layer 2 ----
    agg_kernel<<<agg_blocks, 256>>>(y, ep[2], aggr);
    mma_gemm_kernel<<<mm_blocks, 256, SM_TOT>>>(aggr, whi + 4 * 16384, b1[2], h);
    gemm40_softmax_kernel<<<mm_blocks, 80, G40_SMEM>>>(h, W2[2], b2[2], out);

    (void)in_sizes; (void)n_in; (void)out_size;
}